// round 15
// baseline (speedup 1.0000x reference)
#include <cuda_runtime.h>
#include <cuda_bf16.h>
#include <cstdint>

#define N_NODES 50000
#define N_EDGES 600000
#define D 128
#define NGRAPH 64
#define DOUT 16
#define SCAN_CHUNK 512
#define SCAN_BLKS ((N_NODES + SCAN_CHUNK - 1) / SCAN_CHUNK)   // 98

// ================= device scratch (no allocation allowed) ====================
__device__ __align__(128) float g_h1[N_NODES * D];
__device__ __align__(128) float g_h2[N_NODES * D];
__device__ float g_gcnt[NGRAPH];
__device__ __align__(128) float g_gsum[NGRAPH * D];
__device__ int g_degi[N_NODES];
__device__ int g_rowptr[N_NODES + 1];
__device__ int g_cursor[N_NODES];
__device__ int g_bsum[SCAN_BLKS];
__device__ int g_adj[N_EDGES];
// pre-split bf16 operand planes (row-major [n][128])
__device__ __align__(16) __nv_bfloat16 g_aggh[N_NODES * D];
__device__ __align__(16) __nv_bfloat16 g_aggl[N_NODES * D];
__device__ __align__(16) __nv_bfloat16 g_xh[N_NODES * D];
__device__ __align__(16) __nv_bfloat16 g_xl[N_NODES * D];
__device__ __align__(16) __nv_bfloat16 g_hh0[N_NODES * D];
__device__ __align__(16) __nv_bfloat16 g_hl0[N_NODES * D];
__device__ __align__(16) __nv_bfloat16 g_hh1[N_NODES * D];
__device__ __align__(16) __nv_bfloat16 g_hl1[N_NODES * D];
// split-bf16 weight planes: [layer][o=128][k=256]
__device__ __align__(128) __nv_bfloat16 g_wbh[3 * 32768];
__device__ __align__(128) __nv_bfloat16 g_wbl[3 * 32768];

// ================= helpers ===================================================
__device__ __forceinline__ uint32_t smem_u32(const void* p) {
    uint32_t a;
    asm("{ .reg .u64 t; cvta.to.shared.u64 t, %1; cvt.u32.u64 %0, t; }" : "=r"(a) : "l"(p));
    return a;
}
__device__ __forceinline__ uint32_t pack_hi(float a, float b, uint32_t& lo) {
    __nv_bfloat16 ah = __float2bfloat16(a), bh = __float2bfloat16(b);
    __nv_bfloat16 al = __float2bfloat16(a - __bfloat162float(ah));
    __nv_bfloat16 bl = __float2bfloat16(b - __bfloat162float(bh));
    lo = ((uint32_t)__bfloat16_as_ushort(bl) << 16) | __bfloat16_as_ushort(al);
    return ((uint32_t)__bfloat16_as_ushort(bh) << 16) | __bfloat16_as_ushort(ah);
}
#define LDSM_X4(R, A) \
    asm volatile("ldmatrix.sync.aligned.m8n8.x4.shared.b16 {%0,%1,%2,%3}, [%4];" \
                 : "=r"((R)[0]), "=r"((R)[1]), "=r"((R)[2]), "=r"((R)[3]) : "r"(A))
#define LDSM_X2(R, A) \
    asm volatile("ldmatrix.sync.aligned.m8n8.x2.shared.b16 {%0,%1}, [%2];" \
                 : "=r"((R)[0]), "=r"((R)[1]) : "r"(A))
#define MMA_BF16(C, A, B) \
    asm volatile("mma.sync.aligned.m16n8k16.row.col.f32.bf16.bf16.f32 " \
                 "{%0,%1,%2,%3}, {%4,%5,%6,%7}, {%8,%9}, {%0,%1,%2,%3};" \
                 : "+f"((C)[0]), "+f"((C)[1]), "+f"((C)[2]), "+f"((C)[3]) \
                 : "r"((A)[0]), "r"((A)[1]), "r"((A)[2]), "r"((A)[3]), "r"((B)[0]), "r"((B)[1]))
__device__ __forceinline__ void red_add_v4(float* p, float4 v) {
    asm volatile("red.global.add.v4.f32 [%0], {%1,%2,%3,%4};"
                 :: "l"(p), "f"(v.x), "f"(v.y), "f"(v.z), "f"(v.w) : "memory");
}

// ================= prep: zero + CSR build ===================================
__global__ void zero_small() {
    int i = blockIdx.x * blockDim.x + threadIdx.x;
    if (i < N_NODES) g_degi[i] = 0;
    if (i < NGRAPH * D) g_gsum[i] = 0.f;
    if (i < NGRAPH) g_gcnt[i] = 0.f;
    if (i == 0) g_rowptr[N_NODES] = N_EDGES;
}
__global__ void count_deg(const int* __restrict__ ei) {
    int e = blockIdx.x * blockDim.x + threadIdx.x;
    if (e >= N_EDGES) return;
    int d = min(max(ei[N_EDGES + e], 0), N_NODES - 1);
    atomicAdd(&g_degi[d], 1);
}
__global__ void scan1() {
    __shared__ int s[SCAN_CHUNK];
    int b = blockIdx.x, t = threadIdx.x;
    int i = b * SCAN_CHUNK + t;
    int v = (i < N_NODES) ? g_degi[i] : 0;
    s[t] = v;
    __syncthreads();
#pragma unroll
    for (int off = 1; off < SCAN_CHUNK; off <<= 1) {
        int add = (t >= off) ? s[t - off] : 0;
        __syncthreads();
        s[t] += add;
        __syncthreads();
    }
    if (i < N_NODES) g_rowptr[i] = s[t] - v;
    if (t == SCAN_CHUNK - 1) g_bsum[b] = s[t];
}
__global__ void scan3() {
    __shared__ int sb[SCAN_BLKS];
    __shared__ int spre;
    int b = blockIdx.x, t = threadIdx.x;
    if (t < SCAN_BLKS) sb[t] = g_bsum[t];
    __syncthreads();
    if (t == 0) {
        int acc = 0;
        for (int j = 0; j < b; j++) acc += sb[j];
        spre = acc;
    }
    __syncthreads();
    int i = b * SCAN_CHUNK + t;
    if (i < N_NODES) {
        int r = g_rowptr[i] + spre;
        g_rowptr[i] = r;
        g_cursor[i] = r;
    }
}
__global__ void fill_adj(const int* __restrict__ ei) {
    int e = blockIdx.x * blockDim.x + threadIdx.x;
    if (e >= N_EDGES) return;
    int s = min(max(ei[e], 0), N_NODES - 1);
    int d = min(max(ei[N_EDGES + e], 0), N_NODES - 1);
    int pos = atomicAdd(&g_cursor[d], 1);
    g_adj[pos] = s;
}
__global__ void build_wplanes(const float* __restrict__ w1l, const float* __restrict__ w1r,
                              const float* __restrict__ w2l, const float* __restrict__ w2r,
                              const float* __restrict__ w3l, const float* __restrict__ w3r) {
    int layer = blockIdx.y;
    const float* wl = (layer == 0) ? w1l : (layer == 1) ? w2l : w3l;
    const float* wr = (layer == 0) ? w1r : (layer == 1) ? w2r : w3r;
    int i = blockIdx.x * blockDim.x + threadIdx.x;
    if (i >= 4096) return;
    int o = i >> 5, k0 = (i & 31) * 8;
    const float* src = (k0 < 128) ? (wl + o * 128 + k0) : (wr + o * 128 + (k0 - 128));
    float4 v0 = ((const float4*)src)[0], v1 = ((const float4*)src)[1];
    uint4 hi, lo;
    hi.x = pack_hi(v0.x, v0.y, lo.x);
    hi.y = pack_hi(v0.z, v0.w, lo.y);
    hi.z = pack_hi(v1.x, v1.y, lo.z);
    hi.w = pack_hi(v1.z, v1.w, lo.w);
    *(uint4*)&g_wbh[layer * 32768 + o * 256 + k0] = hi;
    *(uint4*)&g_wbl[layer * 32768 + o * 256 + k0] = lo;
}
// split x once into bf16 hi/lo planes
__global__ void split_x(const float* __restrict__ x) {
    int i = blockIdx.x * blockDim.x + threadIdx.x;   // N_NODES*D/4 = 1.6M
    if (i >= N_NODES * D / 4) return;
    float4 v = ((const float4*)x)[i];
    uint2 hi, lo;
    hi.x = pack_hi(v.x, v.y, lo.x);
    hi.y = pack_hi(v.z, v.w, lo.y);
    ((uint2*)g_xh)[i] = hi;
    ((uint2*)g_xl)[i] = lo;
}

// ================= gather aggregation (writes split mean planes) ============
__global__ __launch_bounds__(256) void gather_agg(const float* __restrict__ x, int sel) {
    int t = blockIdx.x * blockDim.x + threadIdx.x;
    int n = t >> 5, lane = t & 31;
    if (n >= N_NODES) return;
    const float* src = (sel == 0) ? x : (sel == 1 ? g_h1 : g_h2);
    int beg = g_rowptr[n], end = g_rowptr[n + 1];
    float4 a0 = make_float4(0.f, 0.f, 0.f, 0.f);
    float4 a1 = make_float4(0.f, 0.f, 0.f, 0.f);
    for (int base = beg; base < end; base += 32) {
        int idx = base + lane;
        int sv = (idx < end) ? g_adj[idx] : 0;
        int cnt = min(32, end - base);
        int j = 0;
        for (; j + 1 < cnt; j += 2) {
            int s0 = __shfl_sync(0xffffffffu, sv, j);
            int s1 = __shfl_sync(0xffffffffu, sv, j + 1);
            float4 v0 = ((const float4*)(src + (size_t)s0 * D))[lane];
            float4 v1 = ((const float4*)(src + (size_t)s1 * D))[lane];
            a0.x += v0.x; a0.y += v0.y; a0.z += v0.z; a0.w += v0.w;
            a1.x += v1.x; a1.y += v1.y; a1.z += v1.z; a1.w += v1.w;
        }
        if (j < cnt) {
            int s0 = __shfl_sync(0xffffffffu, sv, j);
            float4 v0 = ((const float4*)(src + (size_t)s0 * D))[lane];
            a0.x += v0.x; a0.y += v0.y; a0.z += v0.z; a0.w += v0.w;
        }
    }
    float inv = 1.f / fmaxf((float)(end - beg), 1.f);
    float4 o;
    o.x = (a0.x + a1.x) * inv;
    o.y = (a0.y + a1.y) * inv;
    o.z = (a0.z + a1.z) * inv;
    o.w = (a0.w + a1.w) * inv;
    uint2 hi, lo;
    hi.x = pack_hi(o.x, o.y, lo.x);
    hi.y = pack_hi(o.z, o.w, lo.y);
    *(uint2*)(g_aggh + (size_t)n * D + lane * 4) = hi;
    *(uint2*)(g_aggl + (size_t)n * D + lane * 4) = lo;
}

// ================= split-bf16 mma.sync SAGE-layer GEMM ======================
// M=64 CTA tile, 128 threads (4 warps: 2m x 2n), warp tile 32x64, BK=32.
// A operands arrive pre-split: fill is pure copies.
#define SMSTRIDE 40

__global__ __launch_bounds__(128, 4) void gemm_mma(int in_sel, int out_sel, int po_sel,
                                                   int layer, const float* __restrict__ bias) {
    __shared__ __align__(16) __nv_bfloat16 sAh[64 * SMSTRIDE];
    __shared__ __align__(16) __nv_bfloat16 sAl[64 * SMSTRIDE];
    __shared__ __align__(16) __nv_bfloat16 sBh[128 * SMSTRIDE];
    __shared__ __align__(16) __nv_bfloat16 sBl[128 * SMSTRIDE];

    const __nv_bfloat16* rph = (in_sel == 0) ? g_xh : (in_sel == 1 ? g_hh0 : g_hh1);
    const __nv_bfloat16* rpl = (in_sel == 0) ? g_xl : (in_sel == 1 ? g_hl0 : g_hl1);
    float* hout = (out_sel == 1) ? g_h1 : g_h2;
    __nv_bfloat16* oph = (po_sel == 0) ? g_hh0 : (po_sel == 1 ? g_hh1 : nullptr);
    __nv_bfloat16* opl = (po_sel == 0) ? g_hl0 : (po_sel == 1 ? g_hl1 : nullptr);
    const __nv_bfloat16* wbh = g_wbh + layer * 32768;
    const __nv_bfloat16* wbl = g_wbl + layer * 32768;

    int tid = threadIdx.x;
    int lane = tid & 31, warp = tid >> 5;
    int wm = warp & 1, wn = warp >> 1;
    int m0 = blockIdx.x * 64;

    uint32_t bAh = smem_u32(sAh), bAl = smem_u32(sAl);
    uint32_t bBh = smem_u32(sBh), bBl = smem_u32(sBl);

    float acc[2][8][4];
#pragma unroll
    for (int mt = 0; mt < 2; mt++)
#pragma unroll
        for (int nt = 0; nt < 8; nt++)
#pragma unroll
            for (int q = 0; q < 4; q++) acc[mt][nt][q] = 0.f;

    int a_tile = lane >> 3, a_r = lane & 7;
    int a_row = wm * 32 + (a_tile & 1) * 8 + a_r;
    int a_kof = (a_tile >> 1) * 8;
    int b_row = wn * 64 + (lane & 7);
    int b_kof = ((lane >> 3) & 1) * 8;

    for (int kc = 0; kc < 8; kc++) {
        const __nv_bfloat16* ph = (kc < 4) ? g_aggh : rph;
        const __nv_bfloat16* pl = (kc < 4) ? g_aggl : rpl;
        int kloc = (kc & 3) * 32;
        // ---- fill A: pure uint4 copies; 64 rows x 4 uint4 = 256 per plane ----
#pragma unroll
        for (int it = 0; it < 2; it++) {
            int idx = tid + it * 128;
            int row = idx >> 2, q = idx & 3;
            int m = m0 + row;
            uint4 vh = make_uint4(0, 0, 0, 0), vl = vh;
            if (m < N_NODES) {
                vh = *(const uint4*)(ph + (size_t)m * 128 + kloc + q * 8);
                vl = *(const uint4*)(pl + (size_t)m * 128 + kloc + q * 8);
            }
            *(uint4*)&sAh[row * SMSTRIDE + q * 8] = vh;
            *(uint4*)&sAl[row * SMSTRIDE + q * 8] = vl;
        }
        // ---- fill B: 128 o x 4 uint4 per plane ----
#pragma unroll
        for (int it = 0; it < 4; it++) {
            int idx = tid + it * 128;
            int o = idx >> 2, q = idx & 3;
            *(uint4*)&sBh[o * SMSTRIDE + q * 8] = *(const uint4*)(wbh + o * 256 + kc * 32 + q * 8);
            *(uint4*)&sBl[o * SMSTRIDE + q * 8] = *(const uint4*)(wbl + o * 256 + kc * 32 + q * 8);
        }
        __syncthreads();

#pragma unroll
        for (int ks = 0; ks < 2; ks++) {
            int k16 = ks * 16;
            uint32_t ah[2][4], al[2][4];
#pragma unroll
            for (int mt = 0; mt < 2; mt++) {
                uint32_t off = (uint32_t)((a_row + mt * 16) * SMSTRIDE + k16 + a_kof) * 2;
                LDSM_X4(ah[mt], bAh + off);
                LDSM_X4(al[mt], bAl + off);
            }
#pragma unroll
            for (int nt = 0; nt < 8; nt++) {
                uint32_t bh[2], bl[2];
                uint32_t off = (uint32_t)((b_row + nt * 8) * SMSTRIDE + k16 + b_kof) * 2;
                LDSM_X2(bh, bBh + off);
                LDSM_X2(bl, bBl + off);
#pragma unroll
                for (int mt = 0; mt < 2; mt++) {
                    MMA_BF16(acc[mt][nt], ah[mt], bh);
                    MMA_BF16(acc[mt][nt], ah[mt], bl);
                    MMA_BF16(acc[mt][nt], al[mt], bh);
                }
            }
        }
        __syncthreads();
    }

    int g4 = lane >> 2, q4 = lane & 3;
    float bv[8][2];
#pragma unroll
    for (int nt = 0; nt < 8; nt++) {
        int n = wn * 64 + nt * 8 + q4 * 2;
        bv[nt][0] = __ldg(&bias[n]);
        bv[nt][1] = __ldg(&bias[n + 1]);
    }
#pragma unroll
    for (int mt = 0; mt < 2; mt++) {
#pragma unroll
        for (int h = 0; h < 2; h++) {
            int m = m0 + wm * 32 + mt * 16 + g4 + h * 8;
            if (m < N_NODES) {
#pragma unroll
                for (int nt = 0; nt < 8; nt++) {
                    int n = wn * 64 + nt * 8 + q4 * 2;
                    float2 o;
                    o.x = fmaxf(acc[mt][nt][h * 2 + 0] + bv[nt][0], 0.f);
                    o.y = fmaxf(acc[mt][nt][h * 2 + 1] + bv[nt][1], 0.f);
                    *(float2*)(hout + (size_t)m * 128 + n) = o;
                    if (oph) {
                        uint32_t lo32;
                        uint32_t hi32 = pack_hi(o.x, o.y, lo32);
                        *(uint32_t*)(oph + (size_t)m * 128 + n) = hi32;
                        *(uint32_t*)(opl + (size_t)m * 128 + n) = lo32;
                    }
                }
            }
        }
    }
}

// ================= pool (segment-accumulated, also counts gcnt) =============
__global__ __launch_bounds__(256) void pool2(const int* __restrict__ batch) {
    int warp = threadIdx.x >> 5, lane = threadIdx.x & 31;
    int nb = blockIdx.x * 256;
    float4 acc = make_float4(0.f, 0.f, 0.f, 0.f);
    int cur = -1, cnt = 0;
    for (int j = warp; j < 256; j += 8) {
        int n = nb + j;
        if (n >= N_NODES) break;
        int g = min(max(batch[n], 0), NGRAPH - 1);
        float4 v = ((const float4*)(g_h1 + (size_t)n * D))[lane];
        if (g != cur) {
            if (cur >= 0) {
                red_add_v4(g_gsum + cur * D + lane * 4, acc);
                if (lane == 0) atomicAdd(&g_gcnt[cur], (float)cnt);
            }
            cur = g;
            acc = v;
            cnt = 1;
        } else {
            acc.x += v.x; acc.y += v.y; acc.z += v.z; acc.w += v.w;
            cnt++;
        }
    }
    if (cur >= 0) {
        red_add_v4(g_gsum + cur * D + lane * 4, acc);
        if (lane == 0) atomicAdd(&g_gcnt[cur], (float)cnt);
    }
}
__global__ void finalk(const float* __restrict__ wlin, const float* __restrict__ blin,
                       float* __restrict__ out) {
    int g = blockIdx.x;
    __shared__ float row[128];
    int t = threadIdx.x;
    float inv = 1.f / fmaxf(g_gcnt[g], 1.f);
    row[t] = g_gsum[g * 128 + t] * inv;
    __syncthreads();
    if (t < DOUT) {
        float acc = blin[t];
#pragma unroll 4
        for (int k = 0; k < 128; k++) acc += row[k] * wlin[t * 128 + k];
        out[g * DOUT + t] = acc;
    }
}

// ================= launch ====================================================
extern "C" void kernel_launch(void* const* d_in, const int* in_sizes, int n_in,
                              void* d_out, int out_size) {
    const float* x     = (const float*)d_in[0];
    const int*   ei    = (const int*)d_in[1];
    const int*   batch = (const int*)d_in[2];
    const float* w1l = (const float*)d_in[3];
    const float* b1  = (const float*)d_in[4];
    const float* w1r = (const float*)d_in[5];
    const float* w2l = (const float*)d_in[6];
    const float* b2  = (const float*)d_in[7];
    const float* w2r = (const float*)d_in[8];
    const float* w3l = (const float*)d_in[9];
    const float* b3  = (const float*)d_in[10];
    const float* w3r = (const float*)d_in[11];
    const float* wlin = (const float*)d_in[12];
    const float* blin = (const float*)d_in[13];
    float* out = (float*)d_out;

    zero_small<<<196, 256>>>();
    count_deg<<<(N_EDGES + 255) / 256, 256>>>(ei);
    scan1<<<SCAN_BLKS, SCAN_CHUNK>>>();
    scan3<<<SCAN_BLKS, SCAN_CHUNK>>>();
    fill_adj<<<(N_EDGES + 255) / 256, 256>>>(ei);
    build_wplanes<<<dim3(16, 3), 256>>>(w1l, w1r, w2l, w2r, w3l, w3r);
    split_x<<<(N_NODES * D / 4 + 255) / 256, 256>>>(x);

    const int AGG_BLOCKS = (N_NODES * 32 + 255) / 256;   // 1 warp/node
    const int GEMM_BLOCKS = (N_NODES + 63) / 64;         // 782 M=64 tiles

    gather_agg<<<AGG_BLOCKS, 256>>>(x, 0);
    gemm_mma<<<GEMM_BLOCKS, 128>>>(0, 1, 0, 0, b1);   // A2=x planes, out h1+planes0

    gather_agg<<<AGG_BLOCKS, 256>>>(x, 1);
    gemm_mma<<<GEMM_BLOCKS, 128>>>(1, 2, 1, 1, b2);   // A2=h planes0, out h2+planes1

    gather_agg<<<AGG_BLOCKS, 256>>>(x, 2);
    gemm_mma<<<GEMM_BLOCKS, 128>>>(2, 1, -1, 2, b3);  // A2=h planes1, out h1 only

    pool2<<<(N_NODES + 255) / 256, 256>>>(batch);
    finalk<<<NGRAPH, 128>>>(wlin, blin, out);
}

// round 16
// speedup vs baseline: 1.1374x; 1.1374x over previous
#include <cuda_runtime.h>
#include <cuda_bf16.h>
#include <cstdint>

#define N_NODES 50000
#define N_EDGES 600000
#define D 128
#define NGRAPH 64
#define DOUT 16
#define SCAN_CHUNK 512
#define SCAN_BLKS ((N_NODES + SCAN_CHUNK - 1) / SCAN_CHUNK)   // 98

// ================= device scratch (no allocation allowed) ====================
__device__ __align__(128) float g_agg[N_NODES * D];
__device__ __align__(128) float g_h1[N_NODES * D];
__device__ __align__(128) float g_h2[N_NODES * D];
__device__ float g_gcnt[NGRAPH];
__device__ __align__(128) float g_gsum[NGRAPH * D];
__device__ int g_degi[N_NODES];
__device__ int g_rowptr[N_NODES + 1];
__device__ int g_cursor[N_NODES];
__device__ int g_bsum[SCAN_BLKS];
__device__ int g_adj[N_EDGES];
__device__ __align__(128) __nv_bfloat16 g_wbh[3 * 32768];
__device__ __align__(128) __nv_bfloat16 g_wbl[3 * 32768];

// ================= helpers ===================================================
__device__ __forceinline__ uint32_t smem_u32(const void* p) {
    uint32_t a;
    asm("{ .reg .u64 t; cvta.to.shared.u64 t, %1; cvt.u32.u64 %0, t; }" : "=r"(a) : "l"(p));
    return a;
}
__device__ __forceinline__ uint32_t pack_hi(float a, float b, uint32_t& lo) {
    __nv_bfloat16 ah = __float2bfloat16(a), bh = __float2bfloat16(b);
    __nv_bfloat16 al = __float2bfloat16(a - __bfloat162float(ah));
    __nv_bfloat16 bl = __float2bfloat16(b - __bfloat162float(bh));
    lo = ((uint32_t)__bfloat16_as_ushort(bl) << 16) | __bfloat16_as_ushort(al);
    return ((uint32_t)__bfloat16_as_ushort(bh) << 16) | __bfloat16_as_ushort(ah);
}
#define LDSM_X4(R, A) \
    asm volatile("ldmatrix.sync.aligned.m8n8.x4.shared.b16 {%0,%1,%2,%3}, [%4];" \
                 : "=r"((R)[0]), "=r"((R)[1]), "=r"((R)[2]), "=r"((R)[3]) : "r"(A))
#define LDSM_X2(R, A) \
    asm volatile("ldmatrix.sync.aligned.m8n8.x2.shared.b16 {%0,%1}, [%2];" \
                 : "=r"((R)[0]), "=r"((R)[1]) : "r"(A))
#define MMA_BF16(C, A, B) \
    asm volatile("mma.sync.aligned.m16n8k16.row.col.f32.bf16.bf16.f32 " \
                 "{%0,%1,%2,%3}, {%4,%5,%6,%7}, {%8,%9}, {%0,%1,%2,%3};" \
                 : "+f"((C)[0]), "+f"((C)[1]), "+f"((C)[2]), "+f"((C)[3]) \
                 : "r"((A)[0]), "r"((A)[1]), "r"((A)[2]), "r"((A)[3]), "r"((B)[0]), "r"((B)[1]))
__device__ __forceinline__ void red_add_v4(float* p, float4 v) {
    asm volatile("red.global.add.v4.f32 [%0], {%1,%2,%3,%4};"
                 :: "l"(p), "f"(v.x), "f"(v.y), "f"(v.z), "f"(v.w) : "memory");
}

// ================= prep: zero + CSR build ===================================
__global__ void zero_small() {
    int i = blockIdx.x * blockDim.x + threadIdx.x;
    if (i < N_NODES) g_degi[i] = 0;
    if (i < NGRAPH * D) g_gsum[i] = 0.f;
    if (i < NGRAPH) g_gcnt[i] = 0.f;
    if (i == 0) g_rowptr[N_NODES] = N_EDGES;
}
__global__ void count_deg(const int* __restrict__ ei) {
    int e = blockIdx.x * blockDim.x + threadIdx.x;
    if (e >= N_EDGES) return;
    int d = min(max(ei[N_EDGES + e], 0), N_NODES - 1);
    atomicAdd(&g_degi[d], 1);
}
__global__ void scan1() {
    __shared__ int s[SCAN_CHUNK];
    int b = blockIdx.x, t = threadIdx.x;
    int i = b * SCAN_CHUNK + t;
    int v = (i < N_NODES) ? g_degi[i] : 0;
    s[t] = v;
    __syncthreads();
#pragma unroll
    for (int off = 1; off < SCAN_CHUNK; off <<= 1) {
        int add = (t >= off) ? s[t - off] : 0;
        __syncthreads();
        s[t] += add;
        __syncthreads();
    }
    if (i < N_NODES) g_rowptr[i] = s[t] - v;
    if (t == SCAN_CHUNK - 1) g_bsum[b] = s[t];
}
__global__ void scan3() {
    __shared__ int sb[SCAN_BLKS];
    __shared__ int spre;
    int b = blockIdx.x, t = threadIdx.x;
    if (t < SCAN_BLKS) sb[t] = g_bsum[t];
    __syncthreads();
    if (t == 0) {
        int acc = 0;
        for (int j = 0; j < b; j++) acc += sb[j];
        spre = acc;
    }
    __syncthreads();
    int i = b * SCAN_CHUNK + t;
    if (i < N_NODES) {
        int r = g_rowptr[i] + spre;
        g_rowptr[i] = r;
        g_cursor[i] = r;
    }
}
__global__ void fill_adj(const int* __restrict__ ei) {
    int e = blockIdx.x * blockDim.x + threadIdx.x;
    if (e >= N_EDGES) return;
    int s = min(max(ei[e], 0), N_NODES - 1);
    int d = min(max(ei[N_EDGES + e], 0), N_NODES - 1);
    int pos = atomicAdd(&g_cursor[d], 1);
    g_adj[pos] = s;
}
__global__ void build_wplanes(const float* __restrict__ w1l, const float* __restrict__ w1r,
                              const float* __restrict__ w2l, const float* __restrict__ w2r,
                              const float* __restrict__ w3l, const float* __restrict__ w3r) {
    int layer = blockIdx.y;
    const float* wl = (layer == 0) ? w1l : (layer == 1) ? w2l : w3l;
    const float* wr = (layer == 0) ? w1r : (layer == 1) ? w2r : w3r;
    int i = blockIdx.x * blockDim.x + threadIdx.x;
    if (i >= 4096) return;
    int o = i >> 5, k0 = (i & 31) * 8;
    const float* src = (k0 < 128) ? (wl + o * 128 + k0) : (wr + o * 128 + (k0 - 128));
    float4 v0 = ((const float4*)src)[0], v1 = ((const float4*)src)[1];
    uint4 hi, lo;
    hi.x = pack_hi(v0.x, v0.y, lo.x);
    hi.y = pack_hi(v0.z, v0.w, lo.y);
    hi.z = pack_hi(v1.x, v1.y, lo.z);
    hi.w = pack_hi(v1.z, v1.w, lo.w);
    *(uint4*)&g_wbh[layer * 32768 + o * 256 + k0] = hi;
    *(uint4*)&g_wbl[layer * 32768 + o * 256 + k0] = lo;
}

// ================= gather aggregation (no atomics, writes mean) =============
__global__ __launch_bounds__(256) void gather_agg(const float* __restrict__ x, int sel) {
    int t = blockIdx.x * blockDim.x + threadIdx.x;
    int n = t >> 5, lane = t & 31;
    if (n >= N_NODES) return;
    const float* src = (sel == 0) ? x : (sel == 1 ? g_h1 : g_h2);
    int beg = g_rowptr[n], end = g_rowptr[n + 1];
    float4 a0 = make_float4(0.f, 0.f, 0.f, 0.f);
    float4 a1 = make_float4(0.f, 0.f, 0.f, 0.f);
    for (int base = beg; base < end; base += 32) {
        int idx = base + lane;
        int sv = (idx < end) ? g_adj[idx] : 0;
        int cnt = min(32, end - base);
        int j = 0;
        for (; j + 1 < cnt; j += 2) {
            int s0 = __shfl_sync(0xffffffffu, sv, j);
            int s1 = __shfl_sync(0xffffffffu, sv, j + 1);
            float4 v0 = ((const float4*)(src + (size_t)s0 * D))[lane];
            float4 v1 = ((const float4*)(src + (size_t)s1 * D))[lane];
            a0.x += v0.x; a0.y += v0.y; a0.z += v0.z; a0.w += v0.w;
            a1.x += v1.x; a1.y += v1.y; a1.z += v1.z; a1.w += v1.w;
        }
        if (j < cnt) {
            int s0 = __shfl_sync(0xffffffffu, sv, j);
            float4 v0 = ((const float4*)(src + (size_t)s0 * D))[lane];
            a0.x += v0.x; a0.y += v0.y; a0.z += v0.z; a0.w += v0.w;
        }
    }
    float inv = 1.f / fmaxf((float)(end - beg), 1.f);
    float4 o;
    o.x = (a0.x + a1.x) * inv;
    o.y = (a0.y + a1.y) * inv;
    o.z = (a0.z + a1.z) * inv;
    o.w = (a0.w + a1.w) * inv;
    ((float4*)(g_agg + (size_t)n * D))[lane] = o;
}

// ================= split-bf16 mma.sync SAGE-layer GEMM ======================
// CTA tile 64(m) x 64(n), 128 threads (4 warps: 2m x 2n), warp tile 32x32,
// BK=32, DOUBLE-BUFFERED smem, one __syncthreads per K-chunk, reg prefetch.
#define SMSTRIDE 40

__global__ __launch_bounds__(128, 4) void gemm_mma(const float* __restrict__ xin,
                                                   int in_sel, int out_sel, int layer,
                                                   const float* __restrict__ bias) {
    __shared__ __align__(16) __nv_bfloat16 sAh[2][64 * SMSTRIDE];
    __shared__ __align__(16) __nv_bfloat16 sAl[2][64 * SMSTRIDE];
    __shared__ __align__(16) __nv_bfloat16 sBh[2][64 * SMSTRIDE];
    __shared__ __align__(16) __nv_bfloat16 sBl[2][64 * SMSTRIDE];

    const float* hin = (in_sel == 0) ? xin : (in_sel == 1 ? g_h1 : g_h2);
    float* hout = (out_sel == 1) ? g_h1 : g_h2;
    const __nv_bfloat16* wbh = g_wbh + layer * 32768;
    const __nv_bfloat16* wbl = g_wbl + layer * 32768;

    int tid = threadIdx.x;
    int lane = tid & 31, warp = tid >> 5;
    int wm = warp & 1, wn = warp >> 1;          // 2(m) x 2(n)
    int m0 = blockIdx.x * 64;
    int o0 = blockIdx.y * 64;                   // output-column half

    float acc[2][4][4];
#pragma unroll
    for (int mt = 0; mt < 2; mt++)
#pragma unroll
        for (int nt = 0; nt < 4; nt++)
#pragma unroll
            for (int q = 0; q < 4; q++) acc[mt][nt][q] = 0.f;

    // prefetch registers
    float4 pa[4];
    uint4 pbh[2], pbl[2];

    // fill-thread mapping
    int fa_row = 0, fa_kq = 0;   // computed per-it below
    (void)fa_row; (void)fa_kq;

    auto loadA = [&](int kc) {
        const float* Asrc = (kc < 4) ? g_agg : hin;
        int kloc = (kc & 3) * 32;
#pragma unroll
        for (int it = 0; it < 4; it++) {
            int idx = tid + it * 128;
            int row = idx >> 3, kq = idx & 7;
            int m = m0 + row;
            pa[it] = make_float4(0.f, 0.f, 0.f, 0.f);
            if (m < N_NODES)
                pa[it] = *(const float4*)(Asrc + (size_t)m * 128 + kloc + kq * 4);
        }
    };
    auto storeA = [&](int buf) {
#pragma unroll
        for (int it = 0; it < 4; it++) {
            int idx = tid + it * 128;
            int row = idx >> 3, kq = idx & 7;
            uint2 hi, lo;
            hi.x = pack_hi(pa[it].x, pa[it].y, lo.x);
            hi.y = pack_hi(pa[it].z, pa[it].w, lo.y);
            *(uint2*)&sAh[buf][row * SMSTRIDE + kq * 4] = hi;
            *(uint2*)&sAl[buf][row * SMSTRIDE + kq * 4] = lo;
        }
    };
    auto loadB = [&](int kc) {
#pragma unroll
        for (int it = 0; it < 2; it++) {
            int idx = tid + it * 128;
            int o = idx >> 2, q = idx & 3;
            pbh[it] = *(const uint4*)(wbh + (size_t)(o0 + o) * 256 + kc * 32 + q * 8);
            pbl[it] = *(const uint4*)(wbl + (size_t)(o0 + o) * 256 + kc * 32 + q * 8);
        }
    };
    auto storeB = [&](int buf) {
#pragma unroll
        for (int it = 0; it < 2; it++) {
            int idx = tid + it * 128;
            int o = idx >> 2, q = idx & 3;
            *(uint4*)&sBh[buf][o * SMSTRIDE + q * 8] = pbh[it];
            *(uint4*)&sBl[buf][o * SMSTRIDE + q * 8] = pbl[it];
        }
    };

    uint32_t bAh = smem_u32(sAh), bAl = smem_u32(sAl);
    uint32_t bBh = smem_u32(sBh), bBl = smem_u32(sBl);
    const uint32_t BUFB = 64 * SMSTRIDE * 2;    // bytes per buffer

    int a_tile = lane >> 3, a_r = lane & 7;
    int a_row = wm * 32 + (a_tile & 1) * 8 + a_r;
    int a_kof = (a_tile >> 1) * 8;
    int b_row = wn * 32 + (lane & 7);
    int b_kof = ((lane >> 3) & 1) * 8;

    // prologue
    loadA(0); loadB(0);
    storeA(0); storeB(0);
    __syncthreads();

#pragma unroll
    for (int kc = 0; kc < 8; kc++) {
        int buf = kc & 1;
        if (kc < 7) { loadA(kc + 1); loadB(kc + 1); }
        uint32_t abh = bAh + buf * BUFB, abl = bAl + buf * BUFB;
        uint32_t bbh = bBh + buf * BUFB, bbl = bBl + buf * BUFB;
#pragma unroll
        for (int ks = 0; ks < 2; ks++) {
            int k16 = ks * 16;
            uint32_t ah[2][4], al[2][4];
#pragma unroll
            for (int mt = 0; mt < 2; mt++) {
                uint32_t off = (uint32_t)((a_row + mt * 16) * SMSTRIDE + k16 + a_kof) * 2;
                LDSM_X4(ah[mt], abh + off);
                LDSM_X4(al[mt], abl + off);
            }
#pragma unroll
            for (int nt = 0; nt < 4; nt++) {
                uint32_t bh[2], bl[2];
                uint32_t off = (uint32_t)((b_row + nt * 8) * SMSTRIDE + k16 + b_kof) * 2;
                LDSM_X2(bh, bbh + off);
                LDSM_X2(bl, bbl + off);
#pragma unroll
                for (int mt = 0; mt < 2; mt++) {
                    MMA_BF16(acc[mt][nt], ah[mt], bh);
                    MMA_BF16(acc[mt][nt], ah[mt], bl);
                    MMA_BF16(acc[mt][nt], al[mt], bh);
                }
            }
        }
        if (kc < 7) { storeA(buf ^ 1); storeB(buf ^ 1); }
        __syncthreads();
    }

    // epilogue: bias + relu + store
    int g4 = lane >> 2, q4 = lane & 3;
    float bv[4][2];
#pragma unroll
    for (int nt = 0; nt < 4; nt++) {
        int n = o0 + wn * 32 + nt * 8 + q4 * 2;
        bv[nt][0] = __ldg(&bias[n]);
        bv[nt][1] = __ldg(&bias[n + 1]);
    }
#pragma unroll
    for (int mt = 0; mt < 2; mt++) {
#pragma unroll
        for (int h = 0; h < 2; h++) {
            int m = m0 + wm * 32 + mt * 16 + g4 + h * 8;
            if (m < N_NODES) {
#pragma unroll
                for (int nt = 0; nt < 4; nt++) {
                    int n = o0 + wn * 32 + nt * 8 + q4 * 2;
                    float2 o;
                    o.x = fmaxf(acc[mt][nt][h * 2 + 0] + bv[nt][0], 0.f);
                    o.y = fmaxf(acc[mt][nt][h * 2 + 1] + bv[nt][1], 0.f);
                    *(float2*)(hout + (size_t)m * 128 + n) = o;
                }
            }
        }
    }
}

// ================= pool (segment-accumulated, also counts gcnt) =============
__global__ __launch_bounds__(256) void pool2(const int* __restrict__ batch) {
    int warp = threadIdx.x >> 5, lane = threadIdx.x & 31;
    int nb = blockIdx.x * 256;
    float4 acc = make_float4(0.f, 0.f, 0.f, 0.f);
    int cur = -1, cnt = 0;
    for (int j = warp; j < 256; j += 8) {
        int n = nb + j;
        if (n >= N_NODES) break;
        int g = min(max(batch[n], 0), NGRAPH - 1);
        float4 v = ((const float4*)(g_h1 + (size_t)n * D))[lane];
        if (g != cur) {
            if (cur >= 0) {
                red_add_v4(g_gsum + cur * D + lane * 4, acc);
                if (lane == 0) atomicAdd(&g_gcnt[cur], (float)cnt);
            }
            cur = g;
            acc = v;
            cnt = 1;
        } else {
            acc.x += v.x; acc.y += v.y; acc.z += v.z; acc.w += v.w;
            cnt++;
        }
    }
    if (cur >= 0) {
        red_add_v4(g_gsum + cur * D + lane * 4, acc);
        if (lane == 0) atomicAdd(&g_gcnt[cur], (float)cnt);
    }
}
__global__ void finalk(const float* __restrict__ wlin, const float* __restrict__ blin,
                       float* __restrict__ out) {
    int g = blockIdx.x;
    __shared__ float row[128];
    int t = threadIdx.x;
    float inv = 1.f / fmaxf(g_gcnt[g], 1.f);
    row[t] = g_gsum[g * 128 + t] * inv;
    __syncthreads();
    if (t < DOUT) {
        float acc = blin[t];
#pragma unroll 4
        for (int k = 0; k < 128; k++) acc += row[k] * wlin[t * 128 + k];
        out[g * DOUT + t] = acc;
    }
}

// ================= launch ====================================================
extern "C" void kernel_launch(void* const* d_in, const int* in_sizes, int n_in,
                              void* d_out, int out_size) {
    const float* x     = (const float*)d_in[0];
    const int*   ei    = (const int*)d_in[1];
    const int*   batch = (const int*)d_in[2];
    const float* w1l = (const float*)d_in[3];
    const float* b1  = (const float*)d_in[4];
    const float* w1r = (const float*)d_in[5];
    const float* w2l = (const float*)d_in[6];
    const float* b2  = (const float*)d_in[7];
    const float* w2r = (const float*)d_in[8];
    const float* w3l = (const float*)d_in[9];
    const float* b3  = (const float*)d_in[10];
    const float* w3r = (const float*)d_in[11];
    const float* wlin = (const float*)d_in[12];
    const float* blin = (const float*)d_in[13];
    float* out = (float*)d_out;

    const int AGG_BLOCKS = (N_NODES * 32 + 255) / 256;     // 1 warp/node
    const dim3 GEMM_GRID((N_NODES + 63) / 64, 2);          // 782 x 2 tiles of 64x64

    // launch order puts gather_agg at index 5 for the ncu -s 5 -c 1 window
    zero_small<<<196, 256>>>();                            // 0
    count_deg<<<(N_EDGES + 255) / 256, 256>>>(ei);         // 1
    scan1<<<SCAN_BLKS, SCAN_CHUNK>>>();                    // 2
    scan3<<<SCAN_BLKS, SCAN_CHUNK>>>();                    // 3
    fill_adj<<<(N_EDGES + 255) / 256, 256>>>(ei);          // 4
    gather_agg<<<AGG_BLOCKS, 256>>>(x, 0);                 // 5  <- ncu
    build_wplanes<<<dim3(16, 3), 256>>>(w1l, w1r, w2l, w2r, w3l, w3r);  // 6

    gemm_mma<<<GEMM_GRID, 128>>>(x, 0, 1, 0, b1);

    gather_agg<<<AGG_BLOCKS, 256>>>(x, 1);
    gemm_mma<<<GEMM_GRID, 128>>>(x, 1, 2, 1, b2);

    gather_agg<<<AGG_BLOCKS, 256>>>(x, 2);
    gemm_mma<<<GEMM_GRID, 128>>>(x, 2, 1, 2, b3);

    pool2<<<(N_NODES + 255) / 256, 256>>>(batch);
    finalk<<<NGRAPH, 128>>>(wlin, blin, out);
}